// round 2
// baseline (speedup 1.0000x reference)
#include <cuda_runtime.h>

#define TR     14              // output rows per tile
#define HALO   4               // max dilation
#define TROWS  (TR + 2*HALO)   // 22
#define TCOLS  64              // 56 cols + 4 halo each side
#define W56    56
#define HW     3136            // 56*56
#define WC_N   32
#define C_N    256
#define GRP    8               // C / WC
#define NTHR   (64 * TR)       // 896
#define TILE_ELEMS (TROWS * TCOLS)  // 1408

__global__ __launch_bounds__(NTHR)
void lcd_kernel(const float* __restrict__ x,
                const float* __restrict__ weight,
                const int*   __restrict__ dilation,
                float*       __restrict__ out)
{
    __shared__ float tile[TROWS][TCOLS];

    const int tx  = threadIdx.x;            // 0..63 (col)
    const int ty  = threadIdx.y;            // 0..TR-1 (row in tile)
    const int tid = ty * 64 + tx;           // 0..895
    const int wc  = blockIdx.y;             // 0..31
    const int b   = blockIdx.z;             // 0..7
    const int r0  = blockIdx.x * TR;        // tile top row

    const int d   = __ldg(&dilation[wc]);   // 1..4, uniform per block
    const int h   = r0 + ty;
    const int w   = tx;
    const bool active = (w < W56);

    // ---- load 9 per-pixel weights into registers (reused for all 8 channel groups)
    float wgt[9];
    if (active) {
        const float* wp = weight + ((size_t)(b * WC_N + wc) * 9) * HW + h * W56 + w;
        #pragma unroll
        for (int k = 0; k < 9; k++) wgt[k] = __ldg(wp + k * HW);
    } else {
        #pragma unroll
        for (int k = 0; k < 9; k++) wgt[k] = 0.0f;
    }

    const int dd  = d;
    const int d64 = d * TCOLS;
    const float* srow = &tile[ty + HALO][tx + HALO];

    #pragma unroll 1
    for (int g = 0; g < GRP; g++) {
        const int c = g * WC_N + wc;
        const float* xp = x + (size_t)(b * C_N + c) * HW;

        __syncthreads();   // previous iteration's reads done before overwrite
        // ---- cooperative tile load: 22x64 = 1408 floats, zero-padded halo
        #pragma unroll
        for (int i = 0; i < 2; i++) {
            const int li = tid + i * NTHR;
            if (li < TILE_ELEMS) {
                const int row = li >> 6;        // 0..21
                const int col = li & 63;        // 0..63
                const int gh  = r0 - HALO + row;
                const int gw  = col - HALO;
                float v = 0.0f;
                if (gh >= 0 && gh < W56 && gw >= 0 && gw < W56)
                    v = __ldg(xp + gh * W56 + gw);
                tile[row][col] = v;
            }
        }
        __syncthreads();

        if (active) {
            float acc;
            acc  = wgt[0] * srow[-d64 - dd];
            acc += wgt[1] * srow[-d64     ];
            acc += wgt[2] * srow[-d64 + dd];
            acc += wgt[3] * srow[      -dd];
            acc += wgt[4] * srow[        0];
            acc += wgt[5] * srow[       dd];
            acc += wgt[6] * srow[ d64 - dd];
            acc += wgt[7] * srow[ d64     ];
            acc += wgt[8] * srow[ d64 + dd];
            out[(size_t)(b * C_N + c) * HW + h * W56 + w] = acc;
        }
    }
}

extern "C" void kernel_launch(void* const* d_in, const int* in_sizes, int n_in,
                              void* d_out, int out_size)
{
    const float* x        = (const float*)d_in[0];
    const float* weight   = (const float*)d_in[1];
    const int*   dilation = (const int*)d_in[2];
    float*       out      = (float*)d_out;

    dim3 grid(W56 / TR, WC_N, 8);   // (4, 32, 8)
    dim3 block(64, TR);             // 896 threads
    lcd_kernel<<<grid, block>>>(x, weight, dilation, out);
}

// round 3
// speedup vs baseline: 1.1292x; 1.1292x over previous
#include <cuda_runtime.h>

#define W56    56
#define HW     3136            // 56*56
#define WC_N   32
#define C_N    256
#define GRP    8               // C / WC
#define NTHR   256
#define NPIX_BLK ((HW + NTHR - 1) / NTHR)   // 13 blocks along pixels

__global__ __launch_bounds__(NTHR)
void lcd_kernel(const float* __restrict__ x,
                const float* __restrict__ weight,
                const int*   __restrict__ dilation,
                float*       __restrict__ out)
{
    const int p   = blockIdx.x * NTHR + threadIdx.x;  // pixel index 0..3135
    const int wc  = blockIdx.y;                       // 0..31
    const int b   = blockIdx.z;                       // 0..7
    if (p >= HW) return;

    const int h = p / W56;
    const int w = p - h * W56;
    const int d = __ldg(&dilation[wc]);               // 1..4, uniform per block

    // ---- 9 per-pixel weights into registers (reused across all 8 channel groups)
    float wgt[9];
    {
        const float* wp = weight + ((size_t)(b * WC_N + wc) * 9) * HW + p;
        #pragma unroll
        for (int k = 0; k < 9; k++) wgt[k] = __ldg(wp + k * HW);
    }

    // ---- per-tap source offsets + validity (independent of g, computed once)
    int  off[9];
    bool vld[9];
    #pragma unroll
    for (int kh = 0; kh < 3; kh++) {
        #pragma unroll
        for (int kw = 0; kw < 3; kw++) {
            const int k  = kh * 3 + kw;
            const int hh = h + (kh - 1) * d;
            const int ww = w + (kw - 1) * d;
            vld[k] = ((unsigned)hh < (unsigned)W56) && ((unsigned)ww < (unsigned)W56);
            off[k] = hh * W56 + ww;
        }
    }

    const float* xb = x   + (size_t)b * C_N * HW + (size_t)wc * HW + p * 0;
    float*       ob = out + (size_t)b * C_N * HW + (size_t)wc * HW;

    #pragma unroll 2
    for (int g = 0; g < GRP; g++) {
        const float* xp = xb + (size_t)g * WC_N * HW;
        float v[9];
        #pragma unroll
        for (int k = 0; k < 9; k++)
            v[k] = vld[k] ? __ldg(xp + off[k]) : 0.0f;

        float acc = wgt[0] * v[0];
        #pragma unroll
        for (int k = 1; k < 9; k++) acc += wgt[k] * v[k];

        ob[(size_t)g * WC_N * HW + p] = acc;
    }
}

extern "C" void kernel_launch(void* const* d_in, const int* in_sizes, int n_in,
                              void* d_out, int out_size)
{
    const float* x        = (const float*)d_in[0];
    const float* weight   = (const float*)d_in[1];
    const int*   dilation = (const int*)d_in[2];
    float*       out      = (float*)d_out;

    dim3 grid(NPIX_BLK, WC_N, 8);   // (13, 32, 8)
    dim3 block(NTHR);               // 256 threads
    lcd_kernel<<<grid, block>>>(x, weight, dilation, out);
}

// round 4
// speedup vs baseline: 1.4336x; 1.2695x over previous
#include <cuda_runtime.h>

#define W56   56
#define HW    3136
#define WC_N  32
#define C_N   256
#define GRP   8
#define NTHR  256
#define W4N   14               // float4 per row
#define P4    (W56 * W4N)      // 784 float4-pixels per image

__device__ __forceinline__ float4 zf4() { return make_float4(0.f, 0.f, 0.f, 0.f); }

template<int D>
__device__ __forceinline__ void lcd_body(const float* __restrict__ x,
                                         const float* __restrict__ weight,
                                         float* __restrict__ out,
                                         int b, int wc, int h, int w4)
{
    // 9 taps × 4 pixels of weights, loaded once, reused across all 8 channel groups
    float4 wg[9];
    const float* wp = weight + ((size_t)(b * WC_N + wc) * 9) * HW + h * W56 + w4;
#pragma unroll
    for (int k = 0; k < 9; k++) wg[k] = *(const float4*)(wp + k * HW);

    const float* xb = x   + (size_t)(b * C_N + wc) * HW;
    float*       ob = out + (size_t)(b * C_N + wc) * HW + h * W56 + w4;

#pragma unroll 1
    for (int g = 0; g < GRP; g++) {
        const float* xp = xb + (size_t)g * WC_N * HW;
        float4 acc = zf4();
#pragma unroll
        for (int j = 0; j < 3; j++) {
            const int hh = h + (j - 1) * D;
            const bool rv = (unsigned)hh < (unsigned)W56;
            const float* row = xp + hh * W56 + w4;
            // aligned 12-float span [w4-4, w4+8) with boundary zeroing
            float4 L = (rv && w4 > 0)  ? *(const float4*)(row - 4) : zf4();
            float4 M =  rv             ? *(const float4*)(row)     : zf4();
            float4 R = (rv && w4 < 52) ? *(const float4*)(row + 4) : zf4();
            const float a[12] = {L.x, L.y, L.z, L.w,
                                 M.x, M.y, M.z, M.w,
                                 R.x, R.y, R.z, R.w};
#pragma unroll
            for (int kw = 0; kw < 3; kw++) {
                const int    c  = (kw - 1) * D;       // compile-time
                const float4 wk = wg[j * 3 + kw];
                acc.x += wk.x * a[4 + 0 + c];
                acc.y += wk.y * a[4 + 1 + c];
                acc.z += wk.z * a[4 + 2 + c];
                acc.w += wk.w * a[4 + 3 + c];
            }
        }
        *(float4*)(ob + (size_t)g * WC_N * HW) = acc;
    }
}

__global__ __launch_bounds__(NTHR)
void lcd_kernel(const float* __restrict__ x,
                const float* __restrict__ weight,
                const int*   __restrict__ dilation,
                float*       __restrict__ out)
{
    const int p4 = blockIdx.x * NTHR + threadIdx.x;
    if (p4 >= P4) return;
    const int h  = p4 / W4N;
    const int w4 = (p4 - h * W4N) * 4;
    const int wc = blockIdx.y;
    const int b  = blockIdx.z;
    const int d  = __ldg(&dilation[wc]);   // 1..4, uniform per block

    switch (d) {
        case 1:  lcd_body<1>(x, weight, out, b, wc, h, w4); break;
        case 2:  lcd_body<2>(x, weight, out, b, wc, h, w4); break;
        case 3:  lcd_body<3>(x, weight, out, b, wc, h, w4); break;
        default: lcd_body<4>(x, weight, out, b, wc, h, w4); break;
    }
}

extern "C" void kernel_launch(void* const* d_in, const int* in_sizes, int n_in,
                              void* d_out, int out_size)
{
    const float* x        = (const float*)d_in[0];
    const float* weight   = (const float*)d_in[1];
    const int*   dilation = (const int*)d_in[2];
    float*       out      = (float*)d_out;

    dim3 grid((P4 + NTHR - 1) / NTHR, WC_N, 8);   // (4, 32, 8)
    dim3 block(NTHR);
    lcd_kernel<<<grid, block>>>(x, weight, dilation, out);
}